// round 9
// baseline (speedup 1.0000x reference)
#include <cuda_runtime.h>
#include <math.h>

// ---------------- problem constants ----------------
#define BB 256
#define NN 32
#define HH 256
#define FF 7
#define TT 496
#define RR 8                 // batch rows per 4-CTA cluster
#define NCLUST (BB / RR)     // 32 clusters
#define NCTA (NCLUST * 4)    // 128 CTAs
#define NT 1024
#define KQN 32               // k per octant (8-way K split, gemm)
#define EPSF 1.1920929e-07f

typedef unsigned long long ull;

// ---------------- device scratch ----------------
// gate-interleaved layouts: local col index lc = hcol*4 + gate
__device__ float g_Wc4[4 * HH * 256];    // node combined weights [q][k][lc]
__device__ float g_Wgi4[4 * HH * 256];   // graph Wih [q][k][lc], gate3 = 0
__device__ float g_Wgh4[4 * HH * 256];   // graph Whh [q][k][lc], gate3 = 0
__device__ float g_bv4[4 * 256];         // node combined bias
__device__ float g_bgi4[4 * 256];        // graph ih bias (gate3 = 0)
__device__ float g_bgh4[4 * 256];        // graph hh bias (gate3 = 0)
__device__ float g_PQi4[4 * FF * 256];   // one-hot(i) gathers (gate3 = 0)
__device__ float g_PQj4[4 * FF * 256];
__device__ float g_Ws1T[HH * 64];        // Ws1 transposed [k][u]
__device__ int   g_idx[BB * NN];
__device__ int   g_rd[TT];
__device__ int   g_cd[TT];

// output layout (float32): [x 57344][adj 262144][batch 8192]
#define OUT_X 0
#define OUT_ADJ 57344
#define OUT_BATCH 319488

// ==================== prep kernel ====================
__global__ void prep_kernel(
    const float* __restrict__ nf,
    const float* __restrict__ Wih_n, const float* __restrict__ Whh_n,
    const float* __restrict__ bih_n, const float* __restrict__ bhh_n,
    const float* __restrict__ Wih_g, const float* __restrict__ Whh_g,
    const float* __restrict__ bih_g, const float* __restrict__ bhh_g,
    const float* __restrict__ Ws1,
    float* __restrict__ out)
{
    long t = (long)blockIdx.x * blockDim.x + threadIdx.x;

    if (t < 262144) {   // g_Wc4: [q][k][col*4+g]
        int q = (int)(t >> 16), k = (int)((t >> 8) & 255), lc = (int)(t & 255);
        int g = lc & 3, col = lc >> 2, hc = q * 64 + col;
        float v;
        if (g == 0)      v = Wih_n[hc * 270 + 14 + k] + Whh_n[hc * 256 + k];
        else if (g == 1) v = Wih_n[(256 + hc) * 270 + 14 + k] + Whh_n[(256 + hc) * 256 + k];
        else if (g == 2) v = Wih_n[(512 + hc) * 270 + 14 + k];
        else             v = Whh_n[(512 + hc) * 256 + k];
        g_Wc4[t] = v; return;
    }
    t -= 262144;
    if (t < 262144) {   // g_Wgi4
        int q = (int)(t >> 16), k = (int)((t >> 8) & 255), lc = (int)(t & 255);
        int g = lc & 3, col = lc >> 2, hc = q * 64 + col;
        g_Wgi4[t] = (g < 3) ? Wih_g[(g * 256 + hc) * 256 + k] : 0.f; return;
    }
    t -= 262144;
    if (t < 262144) {   // g_Wgh4
        int q = (int)(t >> 16), k = (int)((t >> 8) & 255), lc = (int)(t & 255);
        int g = lc & 3, col = lc >> 2, hc = q * 64 + col;
        g_Wgh4[t] = (g < 3) ? Whh_g[(g * 256 + hc) * 256 + k] : 0.f; return;
    }
    t -= 262144;
    if (t < 1024) {     // g_bv4
        int q = (int)(t >> 8), lc = (int)(t & 255);
        int g = lc & 3, col = lc >> 2, hc = q * 64 + col;
        float v;
        if (g == 0)      v = bih_n[hc] + bhh_n[hc];
        else if (g == 1) v = bih_n[256 + hc] + bhh_n[256 + hc];
        else if (g == 2) v = bih_n[512 + hc];
        else             v = bhh_n[512 + hc];
        g_bv4[t] = v; return;
    }
    t -= 1024;
    if (t < 1024) {     // g_bgi4
        int q = (int)(t >> 8), lc = (int)(t & 255);
        int g = lc & 3, col = lc >> 2, hc = q * 64 + col;
        g_bgi4[t] = (g < 3) ? bih_g[g * 256 + hc] : 0.f; return;
    }
    t -= 1024;
    if (t < 1024) {     // g_bgh4
        int q = (int)(t >> 8), lc = (int)(t & 255);
        int g = lc & 3, col = lc >> 2, hc = q * 64 + col;
        g_bgh4[t] = (g < 3) ? bhh_g[g * 256 + hc] : 0.f; return;
    }
    t -= 1024;
    if (t < 7168) {     // g_PQi4: [q][f][lc]
        int q = (int)(t / 1792), rem = (int)(t % 1792);
        int f = rem >> 8, lc = rem & 255;
        int g = lc & 3, col = lc >> 2, hc = q * 64 + col;
        g_PQi4[t] = (g < 3) ? Wih_n[(g * 256 + hc) * 270 + f] : 0.f; return;
    }
    t -= 7168;
    if (t < 7168) {     // g_PQj4
        int q = (int)(t / 1792), rem = (int)(t % 1792);
        int f = rem >> 8, lc = rem & 255;
        int g = lc & 3, col = lc >> 2, hc = q * 64 + col;
        g_PQj4[t] = (g < 3) ? Wih_n[(g * 256 + hc) * 270 + 7 + f] : 0.f; return;
    }
    t -= 7168;
    if (t < 16384) {    // W1T [k][u]
        int k = (int)(t >> 6), u = (int)(t & 63);
        g_Ws1T[t] = Ws1[u * 256 + k]; return;
    }
    t -= 16384;
    if (t < BB * NN) {  // argmax one-hot
        const float* p = nf + t * FF;
        int best = 0;
        #pragma unroll
        for (int f = 0; f < FF; f++) if (p[f] > 0.5f) best = f;
        g_idx[t] = best; return;
    }
    t -= BB * NN;
    if (t < TT) {       // anti-diagonal placement
        int m = (int)t;
        int d = (int)((1.0 + sqrt(1.0 + 8.0 * (double)m)) * 0.5);
        while (d * (d - 1) / 2 > m) d--;
        while ((d + 1) * d / 2 <= m) d++;
        int rr = m - d * (d - 1) / 2;
        g_rd[m] = rr; g_cd[m] = rr + NN - d; return;
    }
    t -= TT;
    if (t < BB * NN * FF) { out[OUT_X + t] = nf[t]; return; }
    t -= BB * NN * FF;
    if (t < BB * NN * NN) { out[OUT_ADJ + t] = 0.f; return; }
    t -= BB * NN * NN;
    if (t < BB * NN) { out[OUT_BATCH + t] = (float)(t >> 5); return; }
}

// ==================== helpers ====================
__device__ __forceinline__ float sigm(float x) { return 1.f / (1.f + expf(-x)); }

__device__ __forceinline__ void ffma2(ull& d, ull a, ull b) {
    asm("fma.rn.f32x2 %0, %1, %2, %0;" : "+l"(d) : "l"(a), "l"(b));
}
__device__ __forceinline__ void fadd2(ull& d, ull a) {
    asm("add.rn.f32x2 %0, %0, %1;" : "+l"(d) : "l"(a));
}
__device__ __forceinline__ ull dup2(float w) {
    ull r;
    asm("mov.b64 %0, {%1, %1};" : "=l"(r) : "r"(__float_as_uint(w)));
    return r;
}
__device__ __forceinline__ float2 unpk(ull v) {
    float2 r;
    r.x = __uint_as_float((unsigned)(v & 0xffffffffu));
    r.y = __uint_as_float((unsigned)(v >> 32));
    return r;
}
__device__ __forceinline__ void st_peer64(float* p, unsigned peer, ull bits) {
    unsigned la = (unsigned)__cvta_generic_to_shared(p);
    unsigned ra;
    asm volatile("mapa.shared::cluster.u32 %0, %1, %2;" : "=r"(ra) : "r"(la), "r"(peer));
    asm volatile("st.shared::cluster.b64 [%0], %1;" :: "r"(ra), "l"(bits) : "memory");
}
#define CLUSTER_SYNC() do { \
    asm volatile("barrier.cluster.arrive.aligned;" ::: "memory"); \
    asm volatile("barrier.cluster.wait.aligned;" ::: "memory"); } while (0)

// ---- gemm: thread owns gate-pair (2 cols) of one h-col, 32 k, 8 rows ----
// acc[g*4+p] = f32x2 rows (2p,2p+1), local gate g in {0,1}
__device__ __forceinline__ void gbody2(const float2 w, const float* __restrict__ hk,
                                       ull acc[8])
{
    ulonglong2 h01 = *(const ulonglong2*)(hk);
    ulonglong2 h23 = *(const ulonglong2*)(hk + 4);
    ull wd = dup2(w.x);
    ffma2(acc[0], wd, h01.x); ffma2(acc[1], wd, h01.y);
    ffma2(acc[2], wd, h23.x); ffma2(acc[3], wd, h23.y);
    wd = dup2(w.y);
    ffma2(acc[4], wd, h01.x); ffma2(acc[5], wd, h01.y);
    ffma2(acc[6], wd, h23.x); ffma2(acc[7], wd, h23.y);
}

// streamed gemm over 32 k-rows, weight float2 from global (stride 256 floats/k)
__device__ __forceinline__ void gemm32(const float* __restrict__ Wp,
                                       const float* __restrict__ hq, ull acc[8])
{
    float2 wb[4];
    #pragma unroll
    for (int x = 0; x < 4; x++) wb[x] = *(const float2*)(Wp + x * 256);
    #pragma unroll
    for (int blk = 0; blk < KQN / 4; blk++) {
        float2 wc[4];
        #pragma unroll
        for (int x = 0; x < 4; x++) wc[x] = wb[x];
        if (blk + 1 < KQN / 4) {
            const float* np = Wp + (blk + 1) * 4 * 256;
            #pragma unroll
            for (int x = 0; x < 4; x++) wb[x] = *(const float2*)(np + x * 256);
        }
        const float* hkb = hq + blk * 4 * 8;
        #pragma unroll
        for (int x = 0; x < 4; x++) gbody2(wc[x], hkb + x * 8, acc);
    }
}

// ---------------- smem layout (float offsets) ----------------
#define SO_W1T  0                          // 16384
#define SO_HA   (SO_W1T + 16384)           // 16384
#define SO_HB   (SO_HA + 2048)             // 18432
#define SO_GA   (SO_HB + 2048)             // 20480
#define SO_GB   (SO_GA + 2048)             // 22528
#define SO_RED  (SO_GB + 2048)             // 24576  64 slots x 256 floats
#define SO_PQI  (SO_RED + 16384)           // 40960
#define SO_PQJ  (SO_PQI + 1792)            // 42752
#define SO_SPS  (SO_PQJ + 1792)            // 44544  16 kq x 64 u x f32x2
#define SO_SVI  (SO_SPS + 2048)            // 46592  128 x 8 ull
#define SO_SBV  (SO_SVI + 2048)            // 48640
#define SO_SBGI (SO_SBV + 256)             // 48896
#define SO_SBGH (SO_SBGI + 256)            // 49152
#define SO_SP4  (SO_SBGH + 256)            // 49408  2 ull
#define SO_IDX  (SO_SP4 + 4)               // 49412  256 ints
#define SMEM_FLOATS (SO_IDX + 256)         // 49668
#define SMEM_BYTES (SMEM_FLOATS * 4)       // 198672

// ==================== main chain kernel ====================
__global__ void __launch_bounds__(NT, 1) __cluster_dims__(4, 1, 1)
chain_kernel(const float* __restrict__ z, const float* __restrict__ uin,
             const float* __restrict__ bs1, const float* __restrict__ Ws2,
             const float* __restrict__ bs2, float* __restrict__ out)
{
    extern __shared__ float sm[];
    float* sW1T = sm + SO_W1T;
    float* hBuf[2] = { sm + SO_HA, sm + SO_HB };
    float* gBuf[2] = { sm + SO_GA, sm + SO_GB };
    float* sred = sm + SO_RED;
    float* sPQi = sm + SO_PQI;
    float* sPQj = sm + SO_PQJ;
    ull*   sps  = (ull*)(sm + SO_SPS);
    ull*   sVI  = (ull*)(sm + SO_SVI);
    float* sbv  = sm + SO_SBV;
    float* sbgi = sm + SO_SBGI;
    float* sbgh = sm + SO_SBGH;
    ull*   sp4  = (ull*)(sm + SO_SP4);
    int*   sidx = (int*)(sm + SO_IDX);

    const int t = threadIdx.x;
    const int q = blockIdx.x & 3;
    const int cid = blockIdx.x >> 2;
    const int b0 = cid * RR;

    const float* WcG  = g_Wc4  + q * 65536;
    const float* WgiG = g_Wgi4 + q * 65536;
    const float* WghG = g_Wgh4 + q * 65536;

    // ---- init smem ----
    for (int x = t; x < 16384; x += NT) sW1T[x] = g_Ws1T[x];
    for (int x = t; x < FF * 256; x += NT) {
        sPQi[x] = g_PQi4[q * FF * 256 + x];
        sPQj[x] = g_PQj4[q * FF * 256 + x];
    }
    for (int x = t; x < 2048; x += NT) {      // graph h init [k][8]
        int k = x >> 3, r = x & 7;
        gBuf[0][x] = z[(b0 + r) * HH + k];
    }
    for (int x = t; x < 256; x += NT) { }     // (no-op, NT>256)
    if (t < 256) {
        sbv[t]  = g_bv4[q * 256 + t];
        sbgi[t] = g_bgi4[q * 256 + t];
        sbgh[t] = g_bgh4[q * 256 + t];
        sidx[t] = g_idx[b0 * NN + t];
    }

    // gemm role: gate-pair of one col, one octant
    const int ch  = t & 127;
    const int col = ch >> 1;
    const int gp  = ch & 1;
    const int oct = t >> 7;
    const float* WcT  = WcG  + col * 4 + gp * 2;
    const float* WgiT = WgiG + col * 4 + gp * 2;
    const float* WghT = WghG + col * 4 + gp * 2;
    // reduce role (t < 128)
    const int rcol = t & 63;
    const int ph   = (t >> 6) & 1;
    const int hcr  = q * 64 + rcol;
    // score role
    const int su  = t & 63;
    const int skq = t >> 6;                  // 0..15
    const float b1r  = bs1[su];
    const float w2r  = Ws2[su];
    const float bs2v = *bs2;
    __syncthreads();
    CLUSTER_SYNC();

    int pb = 0, gpb = 0;

    for (int i = 0; i < NN - 1; i++) {
        pb = 0;
        {   // node_h := graph_h
            const float* gs = gBuf[gpb];
            float* d = hBuf[0];
            for (int x = t; x < 2048; x += NT) d[x] = gs[x];
        }
        __syncthreads();

        for (int j = i + 1; j < NN; j++) {
            float* hR = hBuf[pb];
            float* hW = hBuf[pb ^ 1];

            // ---- node gemm: octant oct ----
            ull acc[8];
            #pragma unroll
            for (int x = 0; x < 8; x++) acc[x] = 0ull;
            gemm32(WcT + oct * KQN * 256, hR + oct * KQN * 8, acc);

            // stage: slot = oct*8 + gate_global*2 + pp
            #pragma unroll
            for (int g = 0; g < 2; g++) {
                int gg = gp * 2 + g;
                #pragma unroll
                for (int pp = 0; pp < 2; pp++) {
                    *(ulonglong2*)(sred + ((oct * 8 + gg * 2 + pp) * 256 + col * 4)) =
                        make_ulonglong2(acc[g * 4 + 2 * pp], acc[g * 4 + 2 * pp + 1]);
                }
            }
            __syncthreads();

            // ---- reduce + in-register GRU activation (t < 128) ----
            if (t < 128) {
                ull s0[4], s1[4];
                #pragma unroll
                for (int g = 0; g < 4; g++) {
                    s0[g] = 0ull; s1[g] = 0ull;
                    #pragma unroll
                    for (int o = 0; o < 8; o++) {
                        ulonglong2 v = *(const ulonglong2*)
                            (sred + ((o * 8 + g * 2 + ph) * 256 + rcol * 4));
                        fadd2(s0[g], v.x); fadd2(s1[g], v.y);
                    }
                }
                float4 bv4 = *(const float4*)(sbv + rcol * 4);
                float bva[4] = { bv4.x, bv4.y, bv4.z, bv4.w };
                float vg[4][4];
                #pragma unroll
                for (int g = 0; g < 4; g++) {
                    float2 a = unpk(s0[g]), b = unpk(s1[g]);
                    vg[g][0] = a.x + bva[g]; vg[g][1] = a.y + bva[g];
                    vg[g][2] = b.x + bva[g]; vg[g][3] = b.y + bva[g];
                }
                #pragma unroll
                for (int r = 0; r < 4; r++) {
                    int rb = ph * 4 + r;
                    int fi = sidx[rb * NN + i];
                    int fj = sidx[rb * NN + j];
                    float4 pi = *(const float4*)(sPQi + fi * 256 + rcol * 4);
                    float4 pj = *(const float4*)(sPQj + fj * 256 + rcol * 4);
                    vg[0][r] += pi.x + pj.x;
                    vg[1][r] += pi.y + pj.y;
                    vg[2][r] += pi.z + pj.z;
                }
                float4 ho4 = *(const float4*)(hR + hcr * 8 + ph * 4);
                float ho[4] = { ho4.x, ho4.y, ho4.z, ho4.w };
                float hn[4];
                #pragma unroll
                for (int r = 0; r < 4; r++) {
                    float gr = sigm(vg[0][r]);
                    float gz = sigm(vg[1][r]);
                    float gn = tanhf(vg[2][r] + gr * vg[3][r]);
                    hn[r] = (1.f - gz) * gn + gz * ho[r];
                }
                ull lo = ((ull)__float_as_uint(hn[1]) << 32) | (ull)__float_as_uint(hn[0]);
                ull hi = ((ull)__float_as_uint(hn[3]) << 32) | (ull)__float_as_uint(hn[2]);
                float* dp = hW + hcr * 8 + ph * 4;
                ((ull*)dp)[0] = lo; ((ull*)dp)[1] = hi;
                #pragma unroll
                for (int pr = 0; pr < 4; pr++) {
                    if (pr != q) {
                        st_peer64(dp, (unsigned)pr, lo);
                        st_peer64(dp + 2, (unsigned)pr, hi);
                    }
                }
            }
            CLUSTER_SYNC();

            // ---- f32x2 score head over CTA's row-pair (rows 2q, 2q+1) ----
            {
                ull sa = 0ull;
                const float* wp = sW1T + skq * 16 * 64 + su;
                const float* hp = hW + skq * 16 * 8 + 2 * q;
                #pragma unroll
                for (int k = 0; k < 16; k++) {
                    ull hpair = *(const ull*)(hp + k * 8);
                    ffma2(sa, dup2(wp[k * 64]), hpair);
                }
                sps[skq * 64 + su] = sa;
            }
            __syncthreads();
            if (t < 64) {
                ull sum = 0ull;
                #pragma unroll
                for (int x = 0; x < 16; x++) fadd2(sum, sps[x * 64 + t]);
                float2 s = unpk(sum);
                float hx = fmaxf(s.x + b1r, 0.f) * w2r;
                float hy = fmaxf(s.y + b1r, 0.f) * w2r;
                ull sc = ((ull)__float_as_uint(hy) << 32) | (ull)__float_as_uint(hx);
                #pragma unroll
                for (int o = 16; o; o >>= 1) {
                    ull other = __shfl_down_sync(0xffffffffu, sc, o);
                    fadd2(sc, other);
                }
                if ((t & 31) == 0) sp4[t >> 5] = sc;
                asm volatile("bar.sync 2, 64;" ::: "memory");
                if (t < 2) {
                    ull tot = sp4[0];
                    fadd2(tot, sp4[1]);
                    float2 v = unpk(tot);
                    float val = t ? v.y : v.x;
                    float prob = sigm(val + bs2v);
                    int m = i * (NN - 1) - (i * (i - 1)) / 2 + (j - i - 1);
                    int b = b0 + 2 * q + t;
                    float uu = uin[b * TT + m];
                    float pc = fminf(fmaxf(prob, EPSF), 1.f - EPSF);
                    float e;
                    if (pc < 0.499f || pc > 0.501f) {
                        e = (log1pf(-pc + uu * (2.f * pc - 1.f)) - log1pf(-pc))
                          / (logf(pc) - log1pf(-pc));
                    } else {
                        e = uu;
                    }
                    int rr = g_rd[m], cc = g_cd[m];
                    float* adj = out + OUT_ADJ + b * (NN * NN);
                    adj[rr * NN + cc] = e;
                    adj[cc * NN + rr] = e;
                }
            }
            pb ^= 1;
        }

        // ---- graph GRU: two passes sharing the staging region ----
        if (i < NN - 2) {
            const float* hfin = hBuf[pb];
            const float* ghR = gBuf[gpb];
            float* ghW = gBuf[gpb ^ 1];

            // pass 1: gi = Wgi @ hfin
            {
                ull acc[8];
                #pragma unroll
                for (int x = 0; x < 8; x++) acc[x] = 0ull;
                gemm32(WgiT + oct * KQN * 256, hfin + oct * KQN * 8, acc);
                #pragma unroll
                for (int g = 0; g < 2; g++) {
                    int gg = gp * 2 + g;
                    #pragma unroll
                    for (int pp = 0; pp < 2; pp++) {
                        *(ulonglong2*)(sred + ((oct * 8 + gg * 2 + pp) * 256 + col * 4)) =
                            make_ulonglong2(acc[g * 4 + 2 * pp], acc[g * 4 + 2 * pp + 1]);
                    }
                }
            }
            __syncthreads();
            if (t < 128) {
                #pragma unroll
                for (int g = 0; g < 4; g++) {
                    ull s0 = 0ull, s1 = 0ull;
                    #pragma unroll
                    for (int o = 0; o < 8; o++) {
                        ulonglong2 v = *(const ulonglong2*)
                            (sred + ((o * 8 + g * 2 + ph) * 256 + rcol * 4));
                        fadd2(s0, v.x); fadd2(s1, v.y);
                    }
                    sVI[t * 8 + g * 2] = s0;
                    sVI[t * 8 + g * 2 + 1] = s1;
                }
            }
            __syncthreads();

            // pass 2: gh = Wgh @ ghR
            {
                ull acc[8];
                #pragma unroll
                for (int x = 0; x < 8; x++) acc[x] = 0ull;
                gemm32(WghT + oct * KQN * 256, ghR + oct * KQN * 8, acc);
                #pragma unroll
                for (int g = 0; g < 2; g++) {
                    int gg = gp * 2 + g;
                    #pragma unroll
                    for (int pp = 0; pp < 2; pp++) {
                        *(ulonglong2*)(sred + ((oct * 8 + gg * 2 + pp) * 256 + col * 4)) =
                            make_ulonglong2(acc[g * 4 + 2 * pp], acc[g * 4 + 2 * pp + 1]);
                    }
                }
            }
            __syncthreads();
            if (t < 128) {
                float vi[3][4], vh[3][4];
                float4 bgi4 = *(const float4*)(sbgi + rcol * 4);
                float4 bgh4 = *(const float4*)(sbgh + rcol * 4);
                float bgia[3] = { bgi4.x, bgi4.y, bgi4.z };
                float bgha[3] = { bgh4.x, bgh4.y, bgh4.z };
                #pragma unroll
                for (int g = 0; g < 3; g++) {
                    float2 a = unpk(sVI[t * 8 + g * 2]);
                    float2 b = unpk(sVI[t * 8 + g * 2 + 1]);
                    vi[g][0] = a.x + bgia[g]; vi[g][1] = a.y + bgia[g];
                    vi[g][2] = b.x + bgia[g]; vi[g][3] = b.y + bgia[g];
                    ull s0 = 0ull, s1 = 0ull;
                    #pragma unroll
                    for (int o = 0; o < 8; o++) {
                        ulonglong2 v = *(const ulonglong2*)
                            (sred + ((o * 8 + g * 2 + ph) * 256 + rcol * 4));
                        fadd2(s0, v.x); fadd2(s1, v.y);
                    }
                    float2 c = unpk(s0), d = unpk(s1);
                    vh[g][0] = c.x + bgha[g]; vh[g][1] = c.y + bgha[g];
                    vh[g][2] = d.x + bgha[g]; vh[g][3] = d.y + bgha[g];
                }
                float4 go4 = *(const float4*)(ghR + hcr * 8 + ph * 4);
                float go[4] = { go4.x, go4.y, go4.z, go4.w };
                float hn[4];
                #pragma unroll
                for (int r = 0; r < 4; r++) {
                    float rr = sigm(vi[0][r] + vh[0][r]);
                    float zz = sigm(vi[1][r] + vh[1][r]);
                    float nn = tanhf(vi[2][r] + rr * vh[2][r]);
                    hn[r] = (1.f - zz) * nn + zz * go[r];
                }
                ull lo = ((ull)__float_as_uint(hn[1]) << 32) | (ull)__float_as_uint(hn[0]);
                ull hi = ((ull)__float_as_uint(hn[3]) << 32) | (ull)__float_as_uint(hn[2]);
                float* dp = ghW + hcr * 8 + ph * 4;
                ((ull*)dp)[0] = lo; ((ull*)dp)[1] = hi;
                #pragma unroll
                for (int pr = 0; pr < 4; pr++) {
                    if (pr != q) {
                        st_peer64(dp, (unsigned)pr, lo);
                        st_peer64(dp + 2, (unsigned)pr, hi);
                    }
                }
            }
            CLUSTER_SYNC();
            gpb ^= 1;
        }
    }
}

// ==================== launch ====================
extern "C" void kernel_launch(void* const* d_in, const int* in_sizes, int n_in,
                              void* d_out, int out_size)
{
    const float* z     = (const float*)d_in[0];
    const float* nf    = (const float*)d_in[1];
    const float* u     = (const float*)d_in[2];
    const float* Wih_n = (const float*)d_in[3];
    const float* Whh_n = (const float*)d_in[4];
    const float* bih_n = (const float*)d_in[5];
    const float* bhh_n = (const float*)d_in[6];
    const float* Wih_g = (const float*)d_in[7];
    const float* Whh_g = (const float*)d_in[8];
    const float* bih_g = (const float*)d_in[9];
    const float* bhh_g = (const float*)d_in[10];
    const float* Ws1   = (const float*)d_in[11];
    const float* bs1   = (const float*)d_in[12];
    const float* Ws2   = (const float*)d_in[13];
    const float* bs2   = (const float*)d_in[14];
    float* out = (float*)d_out;

    const long total = 262144L * 3 + 1024 * 3 + 7168 * 2 + 16384
                     + BB * NN + TT + BB * NN * FF + BB * NN * NN + BB * NN;
    int blocks = (int)((total + 255) / 256);
    prep_kernel<<<blocks, 256>>>(nf, Wih_n, Whh_n, bih_n, bhh_n,
                                 Wih_g, Whh_g, bih_g, bhh_g, Ws1, out);

    cudaFuncSetAttribute(chain_kernel,
                         cudaFuncAttributeMaxDynamicSharedMemorySize, SMEM_BYTES);
    chain_kernel<<<NCTA, NT, SMEM_BYTES>>>(z, u, bs1, Ws2, bs2, out);
}